// round 10
// baseline (speedup 1.0000x reference)
#include <cuda_runtime.h>
#include <cuda_bf16.h>
#include <math.h>

#define BMAX 2048
#define KD   256
#define PD   256
#define SD   10
#define SP   5              // sample pairs
#define SROWS 8             // k-rows per pipeline stage
#define NIT  (KD / SROWS)   // 32 stages
#define STAGE_FLOATS (SROWS * PD)      // 2048
#define NTHR 64             // threads per CTA (4 columns each)

// per-batch partial results + completion counter (allocation-free scratch)
__device__ float g_pen[BMAX];
__device__ float g_lmse[BMAX];
__device__ unsigned int g_ctr = 0;

typedef unsigned long long u64;

__device__ __forceinline__ u64 ffma2(u64 a, u64 b, u64 c) {
    u64 d;
    asm("fma.rn.f32x2 %0, %1, %2, %3;" : "=l"(d) : "l"(a), "l"(b), "l"(c));
    return d;
}
__device__ __forceinline__ u64 bcast2(float p) {
    u64 d; unsigned u = __float_as_uint(p);
    asm("mov.b64 %0, {%1, %1};" : "=l"(d) : "r"(u));
    return d;
}
__device__ __forceinline__ void cpa16(unsigned saddr, const float* g) {
    asm volatile("cp.async.cg.shared.global [%0], [%1], 16;" :: "r"(saddr), "l"(g));
}
__device__ __forceinline__ void cpa_commit() {
    asm volatile("cp.async.commit_group;");
}

__global__ __launch_bounds__(NTHR, 5)
void vil_main_kernel(const float* __restrict__ y_pred,
                     const float* __restrict__ y_true,
                     const float* __restrict__ Pp,
                     const float* __restrict__ params,
                     const float* __restrict__ Xs,
                     float* __restrict__ out, int out_size, int Bn)
{
    const int b    = blockIdx.x;
    const int tid  = threadIdx.x;
    const int lane = tid & 31;
    const int w    = tid >> 5;

    __shared__ float2 xsp[SP][KD];                         // masked X, 10 KB
    __shared__ __align__(16) float pool[4 * STAGE_FLOATS]; // 32 KB: P stages, later cacc
    __shared__ float hms[SD];
    __shared__ unsigned int lastflag;

    float (*cacc)[PD] = (float (*)[PD])pool;               // [SD][PD] alias (post-GEMM)

    const int n  = (int)params[b * 3 + 0];
    const int kb = (int)params[b * 3 + 1];
    const int mb = (int)params[b * 3 + 2];
    const int nk = n - kb;

    const float*   Pbase     = Pp + (size_t)b * KD * PD;
    const unsigned pool_base = (unsigned)__cvta_generic_to_shared(pool);

    // per-warp cp.async geometry: warp w owns columns [128w, 128w+128)
    // per stage: 8 rows x 128 cols = 4 KB = 256 x 16B chunks; 8 per lane.
    // chunk c = lane + 32*i : row = c>>5, col-offset = (c&31)*4
    int soff[8];
#pragma unroll
    for (int i = 0; i < 8; i++) {
        int c = lane + 32 * i;
        soff[i] = (c >> 5) * PD + 128 * w + (c & 31) * 4;
    }

    // ---- prologue: each warp issues ITS columns of stages 0..2 ----
#pragma unroll
    for (int it = 0; it < 3; it++) {
        unsigned dst = pool_base + ((it & 3) * STAGE_FLOATS) * 4;
        const float* src = Pbase + it * SROWS * PD;
#pragma unroll
        for (int i = 0; i < 8; i++) cpa16(dst + soff[i] * 4, src + soff[i]);
        cpa_commit();
    }

    // ---- load X[b], masked, packed as (x[2sp][k], x[2sp+1][k]) ----
    const float* Xb = Xs + (size_t)b * SD * KD;
    for (int idx = tid; idx < SP * KD; idx += NTHR) {
        int s = idx >> 8;
        int k = idx & (KD - 1);
        float a = Xb[(2 * s)     * KD + k];
        float c = Xb[(2 * s + 1) * KD + k];
        if (k >= kb) { a = 0.0f; c = 0.0f; }
        xsp[s][k] = make_float2(a, c);
    }
    __syncthreads();   // publish X (only block barrier before epilogue)

    // thread owns columns 4*tid .. 4*tid+3
    u64 acc0[SP], acc1[SP], acc2[SP], acc3[SP];
#pragma unroll
    for (int s = 0; s < SP; s++) { acc0[s] = acc1[s] = acc2[s] = acc3[s] = 0ull; }

    // ---- barrier-free pipelined GEMM mainloop (warp-private columns) ----
    for (int it = 0; it < NIT; it++) {
        if (it <= NIT - 3)      asm volatile("cp.async.wait_group 2;");
        else if (it == NIT - 2) asm volatile("cp.async.wait_group 1;");
        else                    asm volatile("cp.async.wait_group 0;");

        const float* st = pool + (it & 3) * STAGE_FLOATS;
        const int k8 = it * SROWS;

        // hoist this thread's 8 P column-quads (LDS.128, conflict-free)
        float4 pv[SROWS];
#pragma unroll
        for (int u = 0; u < SROWS; u++)
            pv[u] = *(const float4*)&st[u * PD + 4 * tid];

#pragma unroll
        for (int u = 0; u < SROWS; u += 2) {
            u64 a0 = bcast2(pv[u].x),     a1 = bcast2(pv[u].y);
            u64 a2 = bcast2(pv[u].z),     a3 = bcast2(pv[u].w);
            u64 b0 = bcast2(pv[u + 1].x), b1 = bcast2(pv[u + 1].y);
            u64 b2 = bcast2(pv[u + 1].z), b3 = bcast2(pv[u + 1].w);
#pragma unroll
            for (int s = 0; s < SP; s++) {
                // one LDS.128: x sample-pairs for k8+u, k8+u+1 (broadcast)
                const ulonglong2 xq = *(const ulonglong2*)&xsp[s][k8 + u];
                acc0[s] = ffma2(xq.x, a0, acc0[s]);
                acc1[s] = ffma2(xq.x, a1, acc1[s]);
                acc2[s] = ffma2(xq.x, a2, acc2[s]);
                acc3[s] = ffma2(xq.x, a3, acc3[s]);
                acc0[s] = ffma2(xq.y, b0, acc0[s]);
                acc1[s] = ffma2(xq.y, b1, acc1[s]);
                acc2[s] = ffma2(xq.y, b2, acc2[s]);
                acc3[s] = ffma2(xq.y, b3, acc3[s]);
            }
        }

        // issue stage it+3 into ring slot (it-1)&3 — this warp's columns only,
        // already consumed by this warp (sequential), so no cross-warp hazard.
        if (it + 3 < NIT) {
            unsigned dst = pool_base + (((it + 3) & 3) * STAGE_FLOATS) * 4;
            const float* src = Pbase + (it + 3) * SROWS * PD;
#pragma unroll
            for (int i = 0; i < 8; i++) cpa16(dst + soff[i] * 4, src + soff[i]);
            cpa_commit();
        }
    }

    // ---- unpack results into cacc (warp-private columns; alias-safe:
    //      cacc occupies ring slots 0/1, last stage read was slot 3) ----
#pragma unroll
    for (int s = 0; s < SP; s++) {
        float2 v0 = *(float2*)&acc0[s];
        float2 v1 = *(float2*)&acc1[s];
        float2 v2 = *(float2*)&acc2[s];
        float2 v3 = *(float2*)&acc3[s];
        *(float4*)&cacc[2 * s][4 * tid]     = make_float4(v0.x, v1.x, v2.x, v3.x);
        *(float4*)&cacc[2 * s + 1][4 * tid] = make_float4(v0.y, v1.y, v2.y, v3.y);
    }
    __syncthreads();

    // ---- per-sample top-(m+1) via iterative max extraction (1 warp / sample) ----
    for (int s = w; s < SD; s += 2) {
        float v[16];
#pragma unroll
        for (int i = 0; i < 8; i++) {
            int idx = lane + 32 * i;
            float2 xv = xsp[s >> 1][idx];
            float x = (s & 1) ? xv.y : xv.x;
            v[i] = (idx < kb) ? fabsf(x) : -1.0f;
        }
#pragma unroll
        for (int i = 0; i < 8; i++) {
            int j = lane + 32 * i;
            v[8 + i] = (j < nk) ? fabsf(cacc[s][j]) : -1.0f;
        }

        float cmax = 0.0f, cm = 0.0f;
        for (int pass = 0;; pass++) {
            float lm = v[0];
#pragma unroll
            for (int i = 1; i < 16; i++) lm = fmaxf(lm, v[i]);
            float wm = lm;
#pragma unroll
            for (int off = 16; off; off >>= 1)
                wm = fmaxf(wm, __shfl_xor_sync(0xffffffffu, wm, off));
            if (pass == 0)  cmax = wm;
            if (pass == mb) { cm = wm; break; }
            // remove exactly ONE instance of wm (matches sort semantics on ties)
            unsigned bal = __ballot_sync(0xffffffffu, lm == wm);
            int src = __ffs(bal) - 1;
            if (lane == src) {
                bool done = false;
#pragma unroll
                for (int i = 0; i < 16; i++) {
                    if (!done && v[i] == wm) { v[i] = -3.0e38f; done = true; }
                }
            }
        }
        if (lane == 0) hms[s] = cmax / (cm + 1e-9f);
    }
    __syncthreads();

    // ---- per-batch terms + last-CTA-done grid reduction ----
    if (tid == 0) {
        float mh = hms[0];
#pragma unroll
        for (int s = 1; s < SD; s++) mh = fmaxf(mh, hms[s]);
        float yp = y_pred[b];
        float pen = ((mb + 1) <= n) ? fmaxf(mh - yp, 0.0f) : 0.0f;
        g_pen[b] = pen;
        float lp = log2f(fmaxf(yp, 1e-9f));
        float lt = log2f(fmaxf(y_true[b], 1e-9f));
        float d  = lt - lp;
        g_lmse[b] = d * d;
        __threadfence();
        unsigned int old = atomicAdd(&g_ctr, 1u);
        lastflag = (old == (unsigned)(Bn - 1)) ? 1u : 0u;
    }
    __syncthreads();

    if (lastflag) {
        __threadfence();   // acquire: observe all CTAs' g_pen/g_lmse writes
        __shared__ float sp[NTHR], sl[NTHR];
        float p = 0.0f, l = 0.0f;
        for (int i = tid; i < Bn; i += NTHR) { p += g_pen[i]; l += g_lmse[i]; }
        sp[tid] = p; sl[tid] = l;
        __syncthreads();
        for (int o = NTHR / 2; o; o >>= 1) {
            if (tid < o) { sp[tid] += sp[tid + o]; sl[tid] += sl[tid + o]; }
            __syncthreads();
        }
        if (tid == 0) {
            float lmse = sl[0] / (float)Bn;
            float viol = sp[0] / (float)Bn;
            float tot  = lmse + 0.5f * viol;
            if (out_size > 0) out[0] = tot;
            if (out_size > 1) out[1] = lmse;
            if (out_size > 2) out[2] = viol;
            g_ctr = 0;   // reset for next graph replay
        }
    }
}

extern "C" void kernel_launch(void* const* d_in, const int* in_sizes, int n_in,
                              void* d_out, int out_size)
{
    const float* y_pred = (const float*)d_in[0];
    const float* y_true = (const float*)d_in[1];
    const float* Pp     = (const float*)d_in[2];
    const float* params = (const float*)d_in[3];
    const float* Xs     = (const float*)d_in[4];
    float* out = (float*)d_out;

    int Bn = in_sizes[0];
    if (Bn > BMAX) Bn = BMAX;

    vil_main_kernel<<<Bn, NTHR>>>(y_pred, y_true, Pp, params, Xs, out, out_size, Bn);
}

// round 12
// speedup vs baseline: 1.0976x; 1.0976x over previous
#include <cuda_runtime.h>
#include <cuda_bf16.h>
#include <math.h>

#define BMAX 2048
#define KD   256
#define PD   256
#define SD   10
#define SP   5              // sample pairs
#define SROWS 8             // k-rows per pipeline stage
#define NIT  (KD / SROWS)   // 32 stages
#define NSTG 3              // ring stages (prefetch distance 2)
#define STAGE_FLOATS (SROWS * PD)      // 2048
#define NTHR 128            // threads per CTA (2 columns each)

// per-batch partial results + completion counter (allocation-free scratch)
__device__ float g_pen[BMAX];
__device__ float g_lmse[BMAX];
__device__ unsigned int g_ctr = 0;

typedef unsigned long long u64;

__device__ __forceinline__ u64 ffma2(u64 a, u64 b, u64 c) {
    u64 d;
    asm("fma.rn.f32x2 %0, %1, %2, %3;" : "=l"(d) : "l"(a), "l"(b), "l"(c));
    return d;
}
__device__ __forceinline__ u64 bcast2(float p) {
    u64 d; unsigned u = __float_as_uint(p);
    asm("mov.b64 %0, {%1, %1};" : "=l"(d) : "r"(u));
    return d;
}
__device__ __forceinline__ void cpa16(unsigned saddr, const float* g) {
    asm volatile("cp.async.cg.shared.global [%0], [%1], 16;" :: "r"(saddr), "l"(g));
}
__device__ __forceinline__ void cpa_commit() {
    asm volatile("cp.async.commit_group;");
}

__global__ __launch_bounds__(NTHR, 6)
void vil_main_kernel(const float* __restrict__ y_pred,
                     const float* __restrict__ y_true,
                     const float* __restrict__ Pp,
                     const float* __restrict__ params,
                     const float* __restrict__ Xs,
                     float* __restrict__ out, int out_size, int Bn)
{
    const int b    = blockIdx.x;
    const int tid  = threadIdx.x;
    const int lane = tid & 31;
    const int w    = tid >> 5;

    __shared__ float2 xsp[SP][KD];                            // masked X, 10 KB
    __shared__ __align__(16) float pool[NSTG * STAGE_FLOATS]; // 24 KB: P stages, later cacc
    __shared__ float hms[SD];
    __shared__ unsigned int lastflag;

    float (*cacc)[PD] = (float (*)[PD])pool;                  // [SD][PD] alias (post-GEMM)

    const int n  = (int)params[b * 3 + 0];
    const int kb = (int)params[b * 3 + 1];
    const int mb = (int)params[b * 3 + 2];
    const int nk = n - kb;

    const float*   Pbase     = Pp + (size_t)b * KD * PD;
    const unsigned pool_base = (unsigned)__cvta_generic_to_shared(pool);

    // per-warp cp.async geometry: warp w owns columns [64w, 64w+64)
    // per stage: 8 rows x 64 cols = 2 KB = 128 x 16B chunks; 4 per lane.
    // chunk c = lane + 32*i : row = c>>4, col-offset = (c&15)*4
    int soff[4];
#pragma unroll
    for (int i = 0; i < 4; i++) {
        int c = lane + 32 * i;
        soff[i] = (c >> 4) * PD + 64 * w + (c & 15) * 4;
    }

    // ---- prologue: each warp issues ITS columns of stages 0..1 ----
#pragma unroll
    for (int it = 0; it < 2; it++) {
        unsigned dst = pool_base + (it * STAGE_FLOATS) * 4;
        const float* src = Pbase + it * SROWS * PD;
#pragma unroll
        for (int i = 0; i < 4; i++) cpa16(dst + soff[i] * 4, src + soff[i]);
        cpa_commit();
    }

    // ---- load X[b], masked, packed as (x[2sp][k], x[2sp+1][k]) ----
    const float* Xb = Xs + (size_t)b * SD * KD;
    for (int idx = tid; idx < SP * KD; idx += NTHR) {
        int s = idx >> 8;
        int k = idx & (KD - 1);
        float a = Xb[(2 * s)     * KD + k];
        float c = Xb[(2 * s + 1) * KD + k];
        if (k >= kb) { a = 0.0f; c = 0.0f; }
        xsp[s][k] = make_float2(a, c);
    }
    __syncthreads();   // publish X (only block barrier before epilogue)

    // thread owns columns 2*tid and 2*tid+1
    u64 acc0[SP], acc1[SP];
#pragma unroll
    for (int s = 0; s < SP; s++) { acc0[s] = 0ull; acc1[s] = 0ull; }

    int slot = 0, nslot = 2;   // slot of stage `it`; slot receiving stage `it+2`
    // ---- barrier-free pipelined GEMM mainloop (warp-private columns) ----
    for (int it = 0; it < NIT; it++) {
        if (it < NIT - 1) asm volatile("cp.async.wait_group 1;");
        else              asm volatile("cp.async.wait_group 0;");

        const float* st = pool + slot * STAGE_FLOATS;
        const int k8 = it * SROWS;

        // hoist this thread's 8 P column-pairs (LDS.64, conflict-free)
        float2 pv[SROWS];
#pragma unroll
        for (int u = 0; u < SROWS; u++)
            pv[u] = *(const float2*)&st[u * PD + 2 * tid];

#pragma unroll
        for (int u = 0; u < SROWS; u += 2) {
            u64 a0 = bcast2(pv[u].x);       // P[k][2t]
            u64 a1 = bcast2(pv[u].y);       // P[k][2t+1]
            u64 b0 = bcast2(pv[u + 1].x);   // P[k+1][2t]
            u64 b1 = bcast2(pv[u + 1].y);   // P[k+1][2t+1]
#pragma unroll
            for (int s = 0; s < SP; s++) {
                // one LDS.128: x sample-pairs for k8+u, k8+u+1 (broadcast)
                const ulonglong2 xq = *(const ulonglong2*)&xsp[s][k8 + u];
                acc0[s] = ffma2(xq.x, a0, acc0[s]);
                acc1[s] = ffma2(xq.x, a1, acc1[s]);
                acc0[s] = ffma2(xq.y, b0, acc0[s]);
                acc1[s] = ffma2(xq.y, b1, acc1[s]);
            }
        }

        // issue stage it+2 into slot last used by stage it-1 (this warp's columns
        // only; consumed by this warp sequentially => no cross-warp hazard).
        if (it + 2 < NIT) {
            unsigned dst = pool_base + (nslot * STAGE_FLOATS) * 4;
            const float* src = Pbase + (it + 2) * SROWS * PD;
#pragma unroll
            for (int i = 0; i < 4; i++) cpa16(dst + soff[i] * 4, src + soff[i]);
            cpa_commit();
        }
        slot  = (slot  == NSTG - 1) ? 0 : slot + 1;
        nslot = (nslot == NSTG - 1) ? 0 : nslot + 1;
    }

    // ---- unpack results into cacc (warp-private columns; alias-safe:
    //      other warps read stage 31 only at their own columns) ----
#pragma unroll
    for (int s = 0; s < SP; s++) {
        float2 v0 = *(float2*)&acc0[s];   // (sample 2s, 2s+1) @ col 2t
        float2 v1 = *(float2*)&acc1[s];   // (sample 2s, 2s+1) @ col 2t+1
        *(float2*)&cacc[2 * s][2 * tid]     = make_float2(v0.x, v1.x);
        *(float2*)&cacc[2 * s + 1][2 * tid] = make_float2(v0.y, v1.y);
    }
    __syncthreads();

    // ---- per-sample top-(m+1) via iterative max extraction (1 warp / sample) ----
    for (int s = w; s < SD; s += 4) {
        float v[16];
#pragma unroll
        for (int i = 0; i < 8; i++) {
            int idx = lane + 32 * i;
            float2 xv = xsp[s >> 1][idx];
            float x = (s & 1) ? xv.y : xv.x;
            v[i] = (idx < kb) ? fabsf(x) : -1.0f;
        }
#pragma unroll
        for (int i = 0; i < 8; i++) {
            int j = lane + 32 * i;
            v[8 + i] = (j < nk) ? fabsf(cacc[s][j]) : -1.0f;
        }

        float cmax = 0.0f, cm = 0.0f;
        for (int pass = 0;; pass++) {
            float lm = v[0];
#pragma unroll
            for (int i = 1; i < 16; i++) lm = fmaxf(lm, v[i]);
            float wm = lm;
#pragma unroll
            for (int off = 16; off; off >>= 1)
                wm = fmaxf(wm, __shfl_xor_sync(0xffffffffu, wm, off));
            if (pass == 0)  cmax = wm;
            if (pass == mb) { cm = wm; break; }
            // remove exactly ONE instance of wm (matches sort semantics on ties)
            unsigned bal = __ballot_sync(0xffffffffu, lm == wm);
            int src = __ffs(bal) - 1;
            if (lane == src) {
                bool done = false;
#pragma unroll
                for (int i = 0; i < 16; i++) {
                    if (!done && v[i] == wm) { v[i] = -3.0e38f; done = true; }
                }
            }
        }
        if (lane == 0) hms[s] = cmax / (cm + 1e-9f);
    }
    __syncthreads();

    // ---- per-batch terms + last-CTA-done grid reduction ----
    if (tid == 0) {
        float mh = hms[0];
#pragma unroll
        for (int s = 1; s < SD; s++) mh = fmaxf(mh, hms[s]);
        float yp = y_pred[b];
        float pen = ((mb + 1) <= n) ? fmaxf(mh - yp, 0.0f) : 0.0f;
        g_pen[b] = pen;
        float lp = log2f(fmaxf(yp, 1e-9f));
        float lt = log2f(fmaxf(y_true[b], 1e-9f));
        float d  = lt - lp;
        g_lmse[b] = d * d;
        __threadfence();
        unsigned int old = atomicAdd(&g_ctr, 1u);
        lastflag = (old == (unsigned)(Bn - 1)) ? 1u : 0u;
    }
    __syncthreads();

    if (lastflag) {
        __threadfence();   // acquire: observe all CTAs' g_pen/g_lmse writes
        __shared__ float sp[NTHR], sl[NTHR];
        float p = 0.0f, l = 0.0f;
        for (int i = tid; i < Bn; i += NTHR) { p += g_pen[i]; l += g_lmse[i]; }
        sp[tid] = p; sl[tid] = l;
        __syncthreads();
        for (int o = NTHR / 2; o; o >>= 1) {
            if (tid < o) { sp[tid] += sp[tid + o]; sl[tid] += sl[tid + o]; }
            __syncthreads();
        }
        if (tid == 0) {
            float lmse = sl[0] / (float)Bn;
            float viol = sp[0] / (float)Bn;
            float tot  = lmse + 0.5f * viol;
            if (out_size > 0) out[0] = tot;
            if (out_size > 1) out[1] = lmse;
            if (out_size > 2) out[2] = viol;
            g_ctr = 0;   // reset for next graph replay
        }
    }
}

extern "C" void kernel_launch(void* const* d_in, const int* in_sizes, int n_in,
                              void* d_out, int out_size)
{
    const float* y_pred = (const float*)d_in[0];
    const float* y_true = (const float*)d_in[1];
    const float* Pp     = (const float*)d_in[2];
    const float* params = (const float*)d_in[3];
    const float* Xs     = (const float*)d_in[4];
    float* out = (float*)d_out;

    int Bn = in_sizes[0];
    if (Bn > BMAX) Bn = BMAX;

    vil_main_kernel<<<Bn, NTHR>>>(y_pred, y_true, Pp, params, Xs, out, out_size, Bn);
}

// round 13
// speedup vs baseline: 1.1581x; 1.0552x over previous
#include <cuda_runtime.h>
#include <cuda_bf16.h>
#include <math.h>

#define BMAX 2048
#define KD   256
#define PD   256
#define SD   10
#define SP   5              // sample pairs
#define SROWS 8             // k-rows per pipeline stage
#define NIT  (KD / SROWS)   // 32 stages
#define STAGE_FLOATS (SROWS * PD)      // 2048
#define NTHR 128            // threads per CTA (2 columns each)

// per-batch partial results + completion counter (allocation-free scratch)
__device__ float g_pen[BMAX];
__device__ float g_lmse[BMAX];
__device__ unsigned int g_ctr = 0;

typedef unsigned long long u64;

__device__ __forceinline__ u64 ffma2(u64 a, u64 b, u64 c) {
    u64 d;
    asm("fma.rn.f32x2 %0, %1, %2, %3;" : "=l"(d) : "l"(a), "l"(b), "l"(c));
    return d;
}
__device__ __forceinline__ u64 bcast2(float p) {
    u64 d; unsigned u = __float_as_uint(p);
    asm("mov.b64 %0, {%1, %1};" : "=l"(d) : "r"(u));
    return d;
}
__device__ __forceinline__ void cpa16(unsigned saddr, const float* g) {
    asm volatile("cp.async.cg.shared.global [%0], [%1], 16;" :: "r"(saddr), "l"(g));
}
__device__ __forceinline__ void cpa_commit() {
    asm volatile("cp.async.commit_group;");
}

__global__ __launch_bounds__(NTHR, 5)
void vil_main_kernel(const float* __restrict__ y_pred,
                     const float* __restrict__ y_true,
                     const float* __restrict__ Pp,
                     const float* __restrict__ params,
                     const float* __restrict__ Xs,
                     float* __restrict__ out, int out_size, int Bn)
{
    const int b    = blockIdx.x;
    const int tid  = threadIdx.x;
    const int lane = tid & 31;
    const int w    = tid >> 5;

    __shared__ float2 xsp[SP][KD];                         // masked X, 10 KB
    __shared__ __align__(16) float pool[4 * STAGE_FLOATS]; // 32 KB: P stages, later cacc
    __shared__ float hms[SD];
    __shared__ unsigned int lastflag;

    float (*cacc)[PD] = (float (*)[PD])pool;               // [SD][PD] alias (post-GEMM)

    const int n  = (int)params[b * 3 + 0];
    const int kb = (int)params[b * 3 + 1];
    const int mb = (int)params[b * 3 + 2];
    const int nk = n - kb;

    const float*   Pbase     = Pp + (size_t)b * KD * PD;
    const unsigned pool_base = (unsigned)__cvta_generic_to_shared(pool);

    // per-warp cp.async geometry: warp w owns columns [64w, 64w+64)
    // per stage: 8 rows x 64 cols = 2 KB = 128 x 16B chunks; 4 per lane.
    // chunk c = lane + 32*i : row = c>>4, col-offset = (c&15)*4
    int soff[4];
#pragma unroll
    for (int i = 0; i < 4; i++) {
        int c = lane + 32 * i;
        soff[i] = (c >> 4) * PD + 64 * w + (c & 15) * 4;
    }

    // ---- prologue: each warp issues ITS columns of stages 0..2 ----
#pragma unroll
    for (int it = 0; it < 3; it++) {
        unsigned dst = pool_base + ((it & 3) * STAGE_FLOATS) * 4;
        const float* src = Pbase + it * SROWS * PD;
#pragma unroll
        for (int i = 0; i < 4; i++) cpa16(dst + soff[i] * 4, src + soff[i]);
        cpa_commit();
    }

    // ---- load X[b], masked, packed as (x[2sp][k], x[2sp+1][k]) ----
    const float* Xb = Xs + (size_t)b * SD * KD;
    for (int idx = tid; idx < SP * KD; idx += NTHR) {
        int s = idx >> 8;
        int k = idx & (KD - 1);
        float a = Xb[(2 * s)     * KD + k];
        float c = Xb[(2 * s + 1) * KD + k];
        if (k >= kb) { a = 0.0f; c = 0.0f; }
        xsp[s][k] = make_float2(a, c);
    }
    __syncthreads();   // publish X (only block barrier before epilogue)

    // thread owns columns 2*tid and 2*tid+1
    u64 acc0[SP], acc1[SP];
#pragma unroll
    for (int s = 0; s < SP; s++) { acc0[s] = 0ull; acc1[s] = 0ull; }

    // ---- barrier-free pipelined GEMM mainloop (warp-private columns) ----
    for (int it = 0; it < NIT; it++) {
        if (it <= NIT - 3)      asm volatile("cp.async.wait_group 2;");
        else if (it == NIT - 2) asm volatile("cp.async.wait_group 1;");
        else                    asm volatile("cp.async.wait_group 0;");

        const float* st = pool + (it & 3) * STAGE_FLOATS;
        const int k8 = it * SROWS;

        // hoist this thread's 8 P column-pairs (LDS.64, conflict-free)
        float2 pv[SROWS];
#pragma unroll
        for (int u = 0; u < SROWS; u++)
            pv[u] = *(const float2*)&st[u * PD + 2 * tid];

#pragma unroll
        for (int u = 0; u < SROWS; u += 2) {
            u64 a0 = bcast2(pv[u].x);       // P[k][2t]
            u64 a1 = bcast2(pv[u].y);       // P[k][2t+1]
            u64 b0 = bcast2(pv[u + 1].x);   // P[k+1][2t]
            u64 b1 = bcast2(pv[u + 1].y);   // P[k+1][2t+1]
#pragma unroll
            for (int s = 0; s < SP; s++) {
                // one LDS.128: x sample-pairs for k8+u, k8+u+1 (broadcast)
                const ulonglong2 xq = *(const ulonglong2*)&xsp[s][k8 + u];
                acc0[s] = ffma2(xq.x, a0, acc0[s]);
                acc1[s] = ffma2(xq.x, a1, acc1[s]);
                acc0[s] = ffma2(xq.y, b0, acc0[s]);
                acc1[s] = ffma2(xq.y, b1, acc1[s]);
            }
        }

        // issue stage it+3 into ring slot (it-1)&3 — this warp's columns only,
        // already consumed by this warp (sequential), so no cross-warp hazard.
        if (it + 3 < NIT) {
            unsigned dst = pool_base + (((it + 3) & 3) * STAGE_FLOATS) * 4;
            const float* src = Pbase + (it + 3) * SROWS * PD;
#pragma unroll
            for (int i = 0; i < 4; i++) cpa16(dst + soff[i] * 4, src + soff[i]);
            cpa_commit();
        }
    }

    // ---- unpack results into cacc (warp-private columns; alias-safe:
    //      cacc occupies ring slots 0/1, last stage read was slot 3) ----
#pragma unroll
    for (int s = 0; s < SP; s++) {
        float2 v0 = *(float2*)&acc0[s];   // (sample 2s, 2s+1) @ col 2t
        float2 v1 = *(float2*)&acc1[s];   // (sample 2s, 2s+1) @ col 2t+1
        *(float2*)&cacc[2 * s][2 * tid]     = make_float2(v0.x, v1.x);
        *(float2*)&cacc[2 * s + 1][2 * tid] = make_float2(v0.y, v1.y);
    }
    __syncthreads();

    // ---- per-sample top-(m+1) via iterative max extraction (1 warp / sample) ----
    for (int s = w; s < SD; s += 4) {
        float v[16];
#pragma unroll
        for (int i = 0; i < 8; i++) {
            int idx = lane + 32 * i;
            float2 xv = xsp[s >> 1][idx];
            float x = (s & 1) ? xv.y : xv.x;
            v[i] = (idx < kb) ? fabsf(x) : -1.0f;
        }
#pragma unroll
        for (int i = 0; i < 8; i++) {
            int j = lane + 32 * i;
            v[8 + i] = (j < nk) ? fabsf(cacc[s][j]) : -1.0f;
        }

        float cmax = 0.0f, cm = 0.0f;
        for (int pass = 0;; pass++) {
            float lm = v[0];
#pragma unroll
            for (int i = 1; i < 16; i++) lm = fmaxf(lm, v[i]);
            float wm = lm;
#pragma unroll
            for (int off = 16; off; off >>= 1)
                wm = fmaxf(wm, __shfl_xor_sync(0xffffffffu, wm, off));
            if (pass == 0)  cmax = wm;
            if (pass == mb) { cm = wm; break; }
            // remove exactly ONE instance of wm (matches sort semantics on ties)
            unsigned bal = __ballot_sync(0xffffffffu, lm == wm);
            int src = __ffs(bal) - 1;
            if (lane == src) {
                bool done = false;
#pragma unroll
                for (int i = 0; i < 16; i++) {
                    if (!done && v[i] == wm) { v[i] = -3.0e38f; done = true; }
                }
            }
        }
        if (lane == 0) hms[s] = cmax / (cm + 1e-9f);
    }
    __syncthreads();

    // ---- per-batch terms + last-CTA-done grid reduction ----
    if (tid == 0) {
        float mh = hms[0];
#pragma unroll
        for (int s = 1; s < SD; s++) mh = fmaxf(mh, hms[s]);
        float yp = y_pred[b];
        float pen = ((mb + 1) <= n) ? fmaxf(mh - yp, 0.0f) : 0.0f;
        g_pen[b] = pen;
        float lp = log2f(fmaxf(yp, 1e-9f));
        float lt = log2f(fmaxf(y_true[b], 1e-9f));
        float d  = lt - lp;
        g_lmse[b] = d * d;
        __threadfence();
        unsigned int old = atomicAdd(&g_ctr, 1u);
        lastflag = (old == (unsigned)(Bn - 1)) ? 1u : 0u;
    }
    __syncthreads();

    if (lastflag) {
        __threadfence();   // acquire: observe all CTAs' g_pen/g_lmse writes
        __shared__ float sp[NTHR], sl[NTHR];
        float p = 0.0f, l = 0.0f;
        for (int i = tid; i < Bn; i += NTHR) { p += g_pen[i]; l += g_lmse[i]; }
        sp[tid] = p; sl[tid] = l;
        __syncthreads();
        for (int o = NTHR / 2; o; o >>= 1) {
            if (tid < o) { sp[tid] += sp[tid + o]; sl[tid] += sl[tid + o]; }
            __syncthreads();
        }
        if (tid == 0) {
            float lmse = sl[0] / (float)Bn;
            float viol = sp[0] / (float)Bn;
            float tot  = lmse + 0.5f * viol;
            if (out_size > 0) out[0] = tot;
            if (out_size > 1) out[1] = lmse;
            if (out_size > 2) out[2] = viol;
            g_ctr = 0;   // reset for next graph replay
        }
    }
}

extern "C" void kernel_launch(void* const* d_in, const int* in_sizes, int n_in,
                              void* d_out, int out_size)
{
    const float* y_pred = (const float*)d_in[0];
    const float* y_true = (const float*)d_in[1];
    const float* Pp     = (const float*)d_in[2];
    const float* params = (const float*)d_in[3];
    const float* Xs     = (const float*)d_in[4];
    float* out = (float*)d_out;

    int Bn = in_sizes[0];
    if (Bn > BMAX) Bn = BMAX;

    vil_main_kernel<<<Bn, NTHR>>>(y_pred, y_true, Pp, params, Xs, out, out_size, Bn);
}

// round 14
// speedup vs baseline: 1.1735x; 1.0133x over previous
#include <cuda_runtime.h>
#include <cuda_bf16.h>
#include <math.h>

#define BMAX 2048
#define KD   256
#define PD   256
#define SD   10
#define SP   5              // sample pairs
#define SROWS 4             // k-rows per pipeline stage (per warp)
#define NIT2 32             // stages per k-half (128/4)
#define WSTG 512            // floats per warp-stage (4 rows x 128 cols)
#define WREG 2048           // floats per warp pool region (4 slots)
#define NTHR 128            // threads: warp = (k-half, col-half); thread = 4 cols

// per-batch partial results + completion counter (allocation-free scratch)
__device__ float g_pen[BMAX];
__device__ float g_lmse[BMAX];
__device__ unsigned int g_ctr = 0;

typedef unsigned long long u64;

__device__ __forceinline__ u64 ffma2(u64 a, u64 b, u64 c) {
    u64 d;
    asm("fma.rn.f32x2 %0, %1, %2, %3;" : "=l"(d) : "l"(a), "l"(b), "l"(c));
    return d;
}
__device__ __forceinline__ u64 bcast2(float p) {
    u64 d; unsigned u = __float_as_uint(p);
    asm("mov.b64 %0, {%1, %1};" : "=l"(d) : "r"(u));
    return d;
}
__device__ __forceinline__ float2 unpack2(u64 a) {
    float2 r;
    asm("mov.b64 {%0, %1}, %2;" : "=f"(r.x), "=f"(r.y) : "l"(a));
    return r;
}
__device__ __forceinline__ void cpa16(unsigned saddr, const float* g) {
    asm volatile("cp.async.cg.shared.global [%0], [%1], 16;" :: "r"(saddr), "l"(g));
}
__device__ __forceinline__ void cpa_commit() {
    asm volatile("cp.async.commit_group;");
}

__global__ __launch_bounds__(NTHR, 5)
void vil_main_kernel(const float* __restrict__ y_pred,
                     const float* __restrict__ y_true,
                     const float* __restrict__ Pp,
                     const float* __restrict__ params,
                     const float* __restrict__ Xs,
                     float* __restrict__ out, int out_size, int Bn)
{
    const int b    = blockIdx.x;
    const int tid  = threadIdx.x;
    const int lane = tid & 31;
    const int w    = tid >> 5;

    __shared__ float2 xsp[SP][KD];                   // masked X, 10 KB
    __shared__ __align__(16) float pool[4 * WREG];   // 32 KB: per-warp stage rings; later cacc+merge
    __shared__ float hms[SD];
    __shared__ unsigned int lastflag;

    float (*cacc)[PD] = (float (*)[PD])pool;         // [SD][PD] alias (post-GEMM)

    const int n  = (int)params[b * 3 + 0];
    const int kb = (int)params[b * 3 + 1];
    const int mb = (int)params[b * 3 + 2];
    const int nk = n - kb;

    // warp roles: ks = k-half (0/1), ch = col-half (0/1)
    const int ks    = w >> 1;
    const int ch    = w & 1;
    const int k0w   = ks * 128;
    const int cbase = ch * 128;              // warp's 128-column window
    // thread's 4 columns: cbase + 4*lane .. +3

    const float* Pbase  = Pp + (size_t)b * KD * PD;
    const float* PbaseW = Pbase + (size_t)k0w * PD + cbase + lane * 4;  // row r of stage s: + (s*4+r)*PD
    float*       wreg   = pool + w * WREG;
    const unsigned wreg_sh = (unsigned)__cvta_generic_to_shared(pool) + (w * WREG + lane * 4) * 4;

    // ---- prologue: issue this warp's quarter of stages 0..2 ----
#pragma unroll
    for (int it = 0; it < 3; it++) {
        unsigned dst = wreg_sh + (it & 3) * WSTG * 4;
        const float* src = PbaseW + it * SROWS * PD;
#pragma unroll
        for (int r = 0; r < SROWS; r++) cpa16(dst + r * 128 * 4, src + r * PD);
        cpa_commit();
    }

    // ---- load X[b], masked, packed as (x[2sp][k], x[2sp+1][k]) ----
    const float* Xb = Xs + (size_t)b * SD * KD;
    for (int idx = tid; idx < SP * KD; idx += NTHR) {
        int s = idx >> 8;
        int k = idx & (KD - 1);
        float a = Xb[(2 * s)     * KD + k];
        float c = Xb[(2 * s + 1) * KD + k];
        if (k >= kb) { a = 0.0f; c = 0.0f; }
        xsp[s][k] = make_float2(a, c);
    }
    __syncthreads();   // publish X

    // acc[sp][c]: sample-pair sp, column cbase+4*lane+c
    u64 acc[SP][4];
#pragma unroll
    for (int s = 0; s < SP; s++)
#pragma unroll
        for (int c = 0; c < 4; c++) acc[s][c] = 0ull;

    // ---- barrier-free pipelined GEMM mainloop (warp-private quarter) ----
    for (int it = 0; it < NIT2; it++) {
        // issue FIRST: slot (it+3)&3 == (it-1)&3 was consumed by this warp last iter
        if (it + 3 < NIT2) {
            unsigned dst = wreg_sh + ((it + 3) & 3) * WSTG * 4;
            const float* src = PbaseW + (it + 3) * SROWS * PD;
#pragma unroll
            for (int r = 0; r < SROWS; r++) cpa16(dst + r * 128 * 4, src + r * PD);
            cpa_commit();
        }
        // wait: stage `it` resident (pending groups allowed: 3/2/1/0)
        if (it <= NIT2 - 4)      asm volatile("cp.async.wait_group 3;");
        else if (it == NIT2 - 3) asm volatile("cp.async.wait_group 2;");
        else if (it == NIT2 - 2) asm volatile("cp.async.wait_group 1;");
        else                     asm volatile("cp.async.wait_group 0;");

        const float* st = wreg + (it & 3) * WSTG;
        const int kk = k0w + it * SROWS;
#pragma unroll
        for (int u = 0; u < SROWS; u += 2) {
            float4 p0 = *(const float4*)&st[u * 128 + lane * 4];        // P[kk+u][4 cols]
            float4 p1 = *(const float4*)&st[(u + 1) * 128 + lane * 4];  // P[kk+u+1][4 cols]
            u64 a0 = bcast2(p0.x), a1 = bcast2(p0.y), a2 = bcast2(p0.z), a3 = bcast2(p0.w);
            u64 b0 = bcast2(p1.x), b1 = bcast2(p1.y), b2 = bcast2(p1.z), b3 = bcast2(p1.w);
#pragma unroll
            for (int s = 0; s < SP; s++) {
                // one LDS.128: x sample-pairs for kk+u, kk+u+1 (broadcast) -> feeds 8 FFMA2
                const ulonglong2 xq = *(const ulonglong2*)&xsp[s][kk + u];
                acc[s][0] = ffma2(xq.x, a0, acc[s][0]);
                acc[s][1] = ffma2(xq.x, a1, acc[s][1]);
                acc[s][2] = ffma2(xq.x, a2, acc[s][2]);
                acc[s][3] = ffma2(xq.x, a3, acc[s][3]);
                acc[s][0] = ffma2(xq.y, b0, acc[s][0]);
                acc[s][1] = ffma2(xq.y, b1, acc[s][1]);
                acc[s][2] = ffma2(xq.y, b2, acc[s][2]);
                acc[s][3] = ffma2(xq.y, b3, acc[s][3]);
            }
        }
    }

    // ---- k-half merge: ks=1 warps stash partials in their OWN pool regions
    //      (offset < slot-3 region they last read), ks=0 warps add ----
    if (ks == 1) {
        u64* mbuf = (u64*)(pool + w * WREG);   // 20 u64 per lane = 1280 floats < slot3 @1536
#pragma unroll
        for (int s = 0; s < SP; s++)
#pragma unroll
            for (int c = 0; c < 4; c++) mbuf[lane * 20 + s * 4 + c] = acc[s][c];
    }
    __syncthreads();
    if (ks == 0) {
        const u64* mbuf = (const u64*)(pool + (w + 2) * WREG);   // partner warp's stash
#pragma unroll
        for (int s = 0; s < SP; s++) {
            float2 v[4];
#pragma unroll
            for (int c = 0; c < 4; c++) {
                float2 mine = unpack2(acc[s][c]);
                float2 oth  = unpack2(mbuf[lane * 20 + s * 4 + c]);
                v[c] = make_float2(mine.x + oth.x, mine.y + oth.y);
            }
            // cacc rows 2s, 2s+1 at this thread's 4 columns (regions 0..2560 — own/finished area)
            *(float4*)&cacc[2 * s][cbase + 4 * lane]     = make_float4(v[0].x, v[1].x, v[2].x, v[3].x);
            *(float4*)&cacc[2 * s + 1][cbase + 4 * lane] = make_float4(v[0].y, v[1].y, v[2].y, v[3].y);
        }
    }
    __syncthreads();

    // ---- per-sample top-(m+1) via iterative max extraction (1 warp / sample) ----
    for (int s = w; s < SD; s += 4) {
        float v[16];
#pragma unroll
        for (int i = 0; i < 8; i++) {
            int idx = lane + 32 * i;
            float2 xv = xsp[s >> 1][idx];
            float x = (s & 1) ? xv.y : xv.x;
            v[i] = (idx < kb) ? fabsf(x) : -1.0f;
        }
#pragma unroll
        for (int i = 0; i < 8; i++) {
            int j = lane + 32 * i;
            v[8 + i] = (j < nk) ? fabsf(cacc[s][j]) : -1.0f;
        }

        float cmax = 0.0f, cm = 0.0f;
        for (int pass = 0;; pass++) {
            float lm = v[0];
#pragma unroll
            for (int i = 1; i < 16; i++) lm = fmaxf(lm, v[i]);
            float wm = lm;
#pragma unroll
            for (int off = 16; off; off >>= 1)
                wm = fmaxf(wm, __shfl_xor_sync(0xffffffffu, wm, off));
            if (pass == 0)  cmax = wm;
            if (pass == mb) { cm = wm; break; }
            // remove exactly ONE instance of wm (matches sort semantics on ties)
            unsigned bal = __ballot_sync(0xffffffffu, lm == wm);
            int src = __ffs(bal) - 1;
            if (lane == src) {
                bool done = false;
#pragma unroll
                for (int i = 0; i < 16; i++) {
                    if (!done && v[i] == wm) { v[i] = -3.0e38f; done = true; }
                }
            }
        }
        if (lane == 0) hms[s] = cmax / (cm + 1e-9f);
    }
    __syncthreads();

    // ---- per-batch terms + last-CTA-done grid reduction ----
    if (tid == 0) {
        float mh = hms[0];
#pragma unroll
        for (int s = 1; s < SD; s++) mh = fmaxf(mh, hms[s]);
        float yp = y_pred[b];
        float pen = ((mb + 1) <= n) ? fmaxf(mh - yp, 0.0f) : 0.0f;
        g_pen[b] = pen;
        float lp = log2f(fmaxf(yp, 1e-9f));
        float lt = log2f(fmaxf(y_true[b], 1e-9f));
        float d  = lt - lp;
        g_lmse[b] = d * d;
        __threadfence();
        unsigned int old = atomicAdd(&g_ctr, 1u);
        lastflag = (old == (unsigned)(Bn - 1)) ? 1u : 0u;
    }
    __syncthreads();

    if (lastflag) {
        __threadfence();   // acquire: observe all CTAs' g_pen/g_lmse writes
        __shared__ float sp[NTHR], sl[NTHR];
        float p = 0.0f, l = 0.0f;
        for (int i = tid; i < Bn; i += NTHR) { p += g_pen[i]; l += g_lmse[i]; }
        sp[tid] = p; sl[tid] = l;
        __syncthreads();
        for (int o = NTHR / 2; o; o >>= 1) {
            if (tid < o) { sp[tid] += sp[tid + o]; sl[tid] += sl[tid + o]; }
            __syncthreads();
        }
        if (tid == 0) {
            float lmse = sl[0] / (float)Bn;
            float viol = sp[0] / (float)Bn;
            float tot  = lmse + 0.5f * viol;
            if (out_size > 0) out[0] = tot;
            if (out_size > 1) out[1] = lmse;
            if (out_size > 2) out[2] = viol;
            g_ctr = 0;   // reset for next graph replay
        }
    }
}

extern "C" void kernel_launch(void* const* d_in, const int* in_sizes, int n_in,
                              void* d_out, int out_size)
{
    const float* y_pred = (const float*)d_in[0];
    const float* y_true = (const float*)d_in[1];
    const float* Pp     = (const float*)d_in[2];
    const float* params = (const float*)d_in[3];
    const float* Xs     = (const float*)d_in[4];
    float* out = (float*)d_out;

    int Bn = in_sizes[0];
    if (Bn > BMAX) Bn = BMAX;

    vil_main_kernel<<<Bn, NTHR>>>(y_pred, y_true, Pp, params, Xs, out, out_size, Bn);
}

// round 15
// speedup vs baseline: 1.2622x; 1.0756x over previous
#include <cuda_runtime.h>
#include <cuda_bf16.h>
#include <math.h>

#define BMAX 2048
#define KD   256
#define PD   256
#define SD   10
#define SP   5              // sample pairs
#define SROWS 4             // k-rows per pipeline stage (per warp)
#define NIT2 32             // stages per k-half (128/4)
#define WSTG 512            // floats per warp-stage (4 rows x 128 cols)
#define WREG 2048           // floats per warp pool region (4 slots)
#define NTHR 128            // threads: warp = (k-half, col-half); thread = 4 cols

// per-batch partial results + completion counter (allocation-free scratch)
__device__ float g_pen[BMAX];
__device__ float g_lmse[BMAX];
__device__ unsigned int g_ctr = 0;

typedef unsigned long long u64;

__device__ __forceinline__ u64 ffma2(u64 a, u64 b, u64 c) {
    u64 d;
    asm("fma.rn.f32x2 %0, %1, %2, %3;" : "=l"(d) : "l"(a), "l"(b), "l"(c));
    return d;
}
__device__ __forceinline__ u64 bcast2(float p) {
    u64 d; unsigned u = __float_as_uint(p);
    asm("mov.b64 %0, {%1, %1};" : "=l"(d) : "r"(u));
    return d;
}
__device__ __forceinline__ float2 unpack2(u64 a) {
    float2 r;
    asm("mov.b64 {%0, %1}, %2;" : "=f"(r.x), "=f"(r.y) : "l"(a));
    return r;
}
__device__ __forceinline__ void cpa16(unsigned saddr, const float* g) {
    asm volatile("cp.async.cg.shared.global [%0], [%1], 16;" :: "r"(saddr), "l"(g));
}
__device__ __forceinline__ void cpa_commit() {
    asm volatile("cp.async.commit_group;");
}

__global__ __launch_bounds__(NTHR, 5)
void vil_main_kernel(const float* __restrict__ y_pred,
                     const float* __restrict__ y_true,
                     const float* __restrict__ Pp,
                     const float* __restrict__ params,
                     const float* __restrict__ Xs,
                     float* __restrict__ out, int out_size, int Bn)
{
    const int b    = blockIdx.x;
    const int tid  = threadIdx.x;
    const int lane = tid & 31;
    const int w    = tid >> 5;

    __shared__ float2 xsp[SP][KD];                   // masked X, 10 KB
    __shared__ __align__(16) float pool[4 * WREG];   // 32 KB: per-warp stage rings; later cacc+merge
    __shared__ float hms[SD];
    __shared__ unsigned int lastflag;

    float (*cacc)[PD] = (float (*)[PD])pool;         // [SD][PD] alias (post-GEMM)

    const int n  = (int)params[b * 3 + 0];
    const int kb = (int)params[b * 3 + 1];
    const int mb = (int)params[b * 3 + 2];
    const int nk = n - kb;

    // warp roles: ks = k-half (0/1), ch = col-half (0/1)
    const int ks    = w >> 1;
    const int ch    = w & 1;
    const int k0w   = ks * 128;
    const int cbase = ch * 128;              // warp's 128-column window
    // thread's 4 columns: cbase + 4*lane .. +3

    // DEAD-COLUMN SKIP: columns j >= nk are masked to -1 downstream and never
    // contribute — don't load them. Garbage (stale smem) flows only into
    // dead-column accumulators, which the selection mask discards.
    const bool ldp = (cbase + 4 * lane) < nk;

    const float* Pbase  = Pp + (size_t)b * KD * PD;
    const float* PbaseW = Pbase + (size_t)k0w * PD + cbase + lane * 4;  // row r of stage s: + (s*4+r)*PD
    float*       wreg   = pool + w * WREG;
    const unsigned wreg_sh = (unsigned)__cvta_generic_to_shared(pool) + (w * WREG + lane * 4) * 4;

    // ---- prologue: issue this warp's quarter of stages 0..2 (live cols only) ----
#pragma unroll
    for (int it = 0; it < 3; it++) {
        unsigned dst = wreg_sh + (it & 3) * WSTG * 4;
        const float* src = PbaseW + it * SROWS * PD;
        if (ldp) {
#pragma unroll
            for (int r = 0; r < SROWS; r++) cpa16(dst + r * 128 * 4, src + r * PD);
        }
        cpa_commit();
    }

    // ---- load X[b], masked, packed as (x[2sp][k], x[2sp+1][k]) ----
    const float* Xb = Xs + (size_t)b * SD * KD;
    for (int idx = tid; idx < SP * KD; idx += NTHR) {
        int s = idx >> 8;
        int k = idx & (KD - 1);
        float a = Xb[(2 * s)     * KD + k];
        float c = Xb[(2 * s + 1) * KD + k];
        if (k >= kb) { a = 0.0f; c = 0.0f; }
        xsp[s][k] = make_float2(a, c);
    }
    __syncthreads();   // publish X

    // acc[sp][c]: sample-pair sp, column cbase+4*lane+c
    u64 acc[SP][4];
#pragma unroll
    for (int s = 0; s < SP; s++)
#pragma unroll
        for (int c = 0; c < 4; c++) acc[s][c] = 0ull;

    // ---- barrier-free pipelined GEMM mainloop (warp-private quarter) ----
    for (int it = 0; it < NIT2; it++) {
        // issue FIRST: slot (it+3)&3 == (it-1)&3 was consumed by this warp last iter
        if (it + 3 < NIT2) {
            unsigned dst = wreg_sh + ((it + 3) & 3) * WSTG * 4;
            const float* src = PbaseW + (it + 3) * SROWS * PD;
            if (ldp) {
#pragma unroll
                for (int r = 0; r < SROWS; r++) cpa16(dst + r * 128 * 4, src + r * PD);
            }
            cpa_commit();
        }
        // wait: stage `it` resident (pending groups allowed: 3/2/1/0)
        if (it <= NIT2 - 4)      asm volatile("cp.async.wait_group 3;");
        else if (it == NIT2 - 3) asm volatile("cp.async.wait_group 2;");
        else if (it == NIT2 - 2) asm volatile("cp.async.wait_group 1;");
        else                     asm volatile("cp.async.wait_group 0;");

        const float* st = wreg + (it & 3) * WSTG;
        const int kk = k0w + it * SROWS;
#pragma unroll
        for (int u = 0; u < SROWS; u += 2) {
            float4 p0 = *(const float4*)&st[u * 128 + lane * 4];        // P[kk+u][4 cols]
            float4 p1 = *(const float4*)&st[(u + 1) * 128 + lane * 4];  // P[kk+u+1][4 cols]
            u64 a0 = bcast2(p0.x), a1 = bcast2(p0.y), a2 = bcast2(p0.z), a3 = bcast2(p0.w);
            u64 b0 = bcast2(p1.x), b1 = bcast2(p1.y), b2 = bcast2(p1.z), b3 = bcast2(p1.w);
#pragma unroll
            for (int s = 0; s < SP; s++) {
                // one LDS.128: x sample-pairs for kk+u, kk+u+1 (broadcast) -> feeds 8 FFMA2
                const ulonglong2 xq = *(const ulonglong2*)&xsp[s][kk + u];
                acc[s][0] = ffma2(xq.x, a0, acc[s][0]);
                acc[s][1] = ffma2(xq.x, a1, acc[s][1]);
                acc[s][2] = ffma2(xq.x, a2, acc[s][2]);
                acc[s][3] = ffma2(xq.x, a3, acc[s][3]);
                acc[s][0] = ffma2(xq.y, b0, acc[s][0]);
                acc[s][1] = ffma2(xq.y, b1, acc[s][1]);
                acc[s][2] = ffma2(xq.y, b2, acc[s][2]);
                acc[s][3] = ffma2(xq.y, b3, acc[s][3]);
            }
        }
    }

    // ---- k-half merge: ks=1 warps stash partials in their OWN pool regions
    //      (offset < slot-3 region they last read), ks=0 warps add ----
    if (ks == 1) {
        u64* mbuf = (u64*)(pool + w * WREG);   // 20 u64 per lane = 1280 floats < slot3 @1536
#pragma unroll
        for (int s = 0; s < SP; s++)
#pragma unroll
            for (int c = 0; c < 4; c++) mbuf[lane * 20 + s * 4 + c] = acc[s][c];
    }
    __syncthreads();
    if (ks == 0) {
        const u64* mbuf = (const u64*)(pool + (w + 2) * WREG);   // partner warp's stash
#pragma unroll
        for (int s = 0; s < SP; s++) {
            float2 v[4];
#pragma unroll
            for (int c = 0; c < 4; c++) {
                float2 mine = unpack2(acc[s][c]);
                float2 oth  = unpack2(mbuf[lane * 20 + s * 4 + c]);
                v[c] = make_float2(mine.x + oth.x, mine.y + oth.y);
            }
            // cacc rows 2s, 2s+1 at this thread's 4 columns
            *(float4*)&cacc[2 * s][cbase + 4 * lane]     = make_float4(v[0].x, v[1].x, v[2].x, v[3].x);
            *(float4*)&cacc[2 * s + 1][cbase + 4 * lane] = make_float4(v[0].y, v[1].y, v[2].y, v[3].y);
        }
    }
    __syncthreads();

    // ---- per-sample top-(m+1) via iterative max extraction (1 warp / sample) ----
    for (int s = w; s < SD; s += 4) {
        float v[16];
#pragma unroll
        for (int i = 0; i < 8; i++) {
            int idx = lane + 32 * i;
            float2 xv = xsp[s >> 1][idx];
            float x = (s & 1) ? xv.y : xv.x;
            v[i] = (idx < kb) ? fabsf(x) : -1.0f;
        }
#pragma unroll
        for (int i = 0; i < 8; i++) {
            int j = lane + 32 * i;
            v[8 + i] = (j < nk) ? fabsf(cacc[s][j]) : -1.0f;
        }

        float cmax = 0.0f, cm = 0.0f;
        for (int pass = 0;; pass++) {
            float lm = v[0];
#pragma unroll
            for (int i = 1; i < 16; i++) lm = fmaxf(lm, v[i]);
            float wm = lm;
#pragma unroll
            for (int off = 16; off; off >>= 1)
                wm = fmaxf(wm, __shfl_xor_sync(0xffffffffu, wm, off));
            if (pass == 0)  cmax = wm;
            if (pass == mb) { cm = wm; break; }
            // remove exactly ONE instance of wm (matches sort semantics on ties)
            unsigned bal = __ballot_sync(0xffffffffu, lm == wm);
            int src = __ffs(bal) - 1;
            if (lane == src) {
                bool done = false;
#pragma unroll
                for (int i = 0; i < 16; i++) {
                    if (!done && v[i] == wm) { v[i] = -3.0e38f; done = true; }
                }
            }
        }
        if (lane == 0) hms[s] = cmax / (cm + 1e-9f);
    }
    __syncthreads();

    // ---- per-batch terms + last-CTA-done grid reduction ----
    if (tid == 0) {
        float mh = hms[0];
#pragma unroll
        for (int s = 1; s < SD; s++) mh = fmaxf(mh, hms[s]);
        float yp = y_pred[b];
        float pen = ((mb + 1) <= n) ? fmaxf(mh - yp, 0.0f) : 0.0f;
        g_pen[b] = pen;
        float lp = log2f(fmaxf(yp, 1e-9f));
        float lt = log2f(fmaxf(y_true[b], 1e-9f));
        float d  = lt - lp;
        g_lmse[b] = d * d;
        __threadfence();
        unsigned int old = atomicAdd(&g_ctr, 1u);
        lastflag = (old == (unsigned)(Bn - 1)) ? 1u : 0u;
    }
    __syncthreads();

    if (lastflag) {
        __threadfence();   // acquire: observe all CTAs' g_pen/g_lmse writes
        __shared__ float sp[NTHR], sl[NTHR];
        float p = 0.0f, l = 0.0f;
        for (int i = tid; i < Bn; i += NTHR) { p += g_pen[i]; l += g_lmse[i]; }
        sp[tid] = p; sl[tid] = l;
        __syncthreads();
        for (int o = NTHR / 2; o; o >>= 1) {
            if (tid < o) { sp[tid] += sp[tid + o]; sl[tid] += sl[tid + o]; }
            __syncthreads();
        }
        if (tid == 0) {
            float lmse = sl[0] / (float)Bn;
            float viol = sp[0] / (float)Bn;
            float tot  = lmse + 0.5f * viol;
            if (out_size > 0) out[0] = tot;
            if (out_size > 1) out[1] = lmse;
            if (out_size > 2) out[2] = viol;
            g_ctr = 0;   // reset for next graph replay
        }
    }
}

extern "C" void kernel_launch(void* const* d_in, const int* in_sizes, int n_in,
                              void* d_out, int out_size)
{
    const float* y_pred = (const float*)d_in[0];
    const float* y_true = (const float*)d_in[1];
    const float* Pp     = (const float*)d_in[2];
    const float* params = (const float*)d_in[3];
    const float* Xs     = (const float*)d_in[4];
    float* out = (float*)d_out;

    int Bn = in_sizes[0];
    if (Bn > BMAX) Bn = BMAX;

    vil_main_kernel<<<Bn, NTHR>>>(y_pred, y_true, Pp, params, Xs, out, out_size, Bn);
}